// round 1
// baseline (speedup 1.0000x reference)
#include <cuda_runtime.h>

#define N_BATCH 4
#define KCH 4
#define HS 64
#define WS 64
#define PPTS (HS*WS)            /* 4096 points per batch */
#define BLOCK 256
#define QSPLIT 8
#define QCHUNK (PPTS/QSPLIT)    /* 512 q-points per block */

// Per point: {fx,fy,fr,fg | fb,h,s0,s1 | s2,s3,pad,pad}  (features pre-scaled by sqrt(log2 e), h = -0.5*log2e*||f||^2)
__device__ float4 g_pts[N_BATCH * PPTS * 3];
__device__ double g_acc;

__global__ void prep_kernel(const float* __restrict__ images,
                            const float* __restrict__ segs) {
    int idx = blockIdx.x * blockDim.x + threadIdx.x;
    if (idx == 0) g_acc = 0.0;
    if (idx >= N_BATCH * PPTS) return;
    int n = idx / PPTS;
    int p = idx % PPTS;
    int y = p / WS;
    int x = p % WS;

    const float SQL2E = 1.2011224087864498f;   // sqrt(log2(e))
    const float L2E   = 1.4426950408889634f;   // log2(e)

    float fx = (float)x * (SQL2E / 50.0f);     // SIGMA_XY * SCALE = 50
    float fy = (float)y * (SQL2E / 50.0f);

    // images[n][c][2y][2x], H=W=128
    const float* img = images + (size_t)n * 3 * 128 * 128;
    int ro = (2 * y) * 128 + 2 * x;
    float fr = img[0 * 128 * 128 + ro] * (SQL2E / 15.0f);
    float fg = img[1 * 128 * 128 + ro] * (SQL2E / 15.0f);
    float fb = img[2 * 128 * 128 + ro] * (SQL2E / 15.0f);

    // h2 = -0.5 * log2e * ||f||^2  == -0.5 * ||f_scaled||^2 since f_scaled = f*sqrt(log2e)
    float sq = fx * fx + fy * fy + fr * fr + fg * fg + fb * fb;
    float h = -0.5f * sq;
    (void)L2E;

    // 2x2 mean pool of segmentations[n][k][2y:2y+2][2x:2x+2]
    const float* sg = segs + (size_t)n * KCH * 128 * 128;
    float s[KCH];
#pragma unroll
    for (int k = 0; k < KCH; k++) {
        const float* sk = sg + (size_t)k * 128 * 128;
        float v = sk[ro] + sk[ro + 1] + sk[ro + 128] + sk[ro + 129];
        s[k] = v * 0.25f;
    }

    float4* o = g_pts + (size_t)idx * 3;
    o[0] = make_float4(fx, fy, fr, fg);
    o[1] = make_float4(fb, h, s[0], s[1]);
    o[2] = make_float4(s[2], s[3], 0.0f, 0.0f);
}

__device__ __forceinline__ float ex2f(float a) {
    float r;
    asm("ex2.approx.ftz.f32 %0, %1;" : "=f"(r) : "f"(a));
    return r;
}

__global__ void __launch_bounds__(BLOCK) crf_kernel() {
    __shared__ float4 tile[QCHUNK * 3];
    __shared__ float wsum[BLOCK / 32];

    int n  = blockIdx.z;
    int p  = blockIdx.y * BLOCK + threadIdx.x;
    int q0 = blockIdx.x * QCHUNK;

    const float4* base = g_pts + (size_t)n * PPTS * 3;

    // Cooperative load of the q tile (512 points * 3 float4)
    for (int i = threadIdx.x; i < QCHUNK * 3; i += BLOCK)
        tile[i] = base[q0 * 3 + i];

    // Own point (register-resident)
    float4 A = base[p * 3 + 0];
    float4 B = base[p * 3 + 1];
    float4 C = base[p * 3 + 2];
    float pfx = A.x, pfy = A.y, pfr = A.z, pfg = A.w, pfb = B.x, ph = B.y;
    float ps0 = B.z, ps1 = B.w, ps2 = C.x, ps3 = C.y;

    __syncthreads();

    float acc0 = 0.0f, acc1 = 0.0f;
#pragma unroll 4
    for (int j = 0; j < QCHUNK; j += 2) {
        {
            float4 a = tile[j * 3 + 0];
            float4 b = tile[j * 3 + 1];
            float4 c = tile[j * 3 + 2];
            float arg = ph + b.y;
            arg = fmaf(pfx, a.x, arg);
            arg = fmaf(pfy, a.y, arg);
            arg = fmaf(pfr, a.z, arg);
            arg = fmaf(pfg, a.w, arg);
            arg = fmaf(pfb, b.x, arg);
            float t = ps0 * b.z;
            t = fmaf(ps1, b.w, t);
            t = fmaf(ps2, c.x, t);
            t = fmaf(ps3, c.y, t);
            acc0 = fmaf(ex2f(arg), t, acc0);
        }
        {
            float4 a = tile[(j + 1) * 3 + 0];
            float4 b = tile[(j + 1) * 3 + 1];
            float4 c = tile[(j + 1) * 3 + 2];
            float arg = ph + b.y;
            arg = fmaf(pfx, a.x, arg);
            arg = fmaf(pfy, a.y, arg);
            arg = fmaf(pfr, a.z, arg);
            arg = fmaf(pfg, a.w, arg);
            arg = fmaf(pfb, b.x, arg);
            float t = ps0 * b.z;
            t = fmaf(ps1, b.w, t);
            t = fmaf(ps2, c.x, t);
            t = fmaf(ps3, c.y, t);
            acc1 = fmaf(ex2f(arg), t, acc1);
        }
    }

    float acc = acc0 + acc1;

    // Warp reduce
#pragma unroll
    for (int off = 16; off > 0; off >>= 1)
        acc += __shfl_down_sync(0xFFFFFFFFu, acc, off);
    int lane = threadIdx.x & 31;
    int warp = threadIdx.x >> 5;
    if (lane == 0) wsum[warp] = acc;
    __syncthreads();
    if (threadIdx.x == 0) {
        float s = 0.0f;
#pragma unroll
        for (int i = 0; i < BLOCK / 32; i++) s += wsum[i];
        atomicAdd(&g_acc, (double)s);
    }
}

__global__ void finish_kernel(float* __restrict__ out) {
    // loss = WEIGHT * (-sum / N_BATCH)
    out[0] = (float)(g_acc * (-1e-7 / (double)N_BATCH));
}

extern "C" void kernel_launch(void* const* d_in, const int* in_sizes, int n_in,
                              void* d_out, int out_size) {
    const float* images = (const float*)d_in[0];
    const float* segs   = (const float*)d_in[1];

    prep_kernel<<<(N_BATCH * PPTS + 255) / 256, 256>>>(images, segs);

    dim3 grid(QSPLIT, PPTS / BLOCK, N_BATCH);
    crf_kernel<<<grid, BLOCK>>>();

    finish_kernel<<<1, 1>>>((float*)d_out);
}

// round 2
// speedup vs baseline: 1.2364x; 1.2364x over previous
#include <cuda_runtime.h>

#define N_BATCH 4
#define KCH 4
#define HS 64
#define WS 64
#define PPTS (HS*WS)            /* 4096 points per batch */
#define TILE 256                /* p-tile = q-tile = 256 points */
#define NTILES (PPTS/TILE)      /* 16 */
#define BLOCK 256
#define NPAIR (TILE/2)          /* 128 packed q-pairs per tile */

// Pair-packed layout: per point-pair m, 5 float4:
//  v0={fx0,fx1,fy0,fy1} v1={fr0,fr1,fg0,fg1} v2={fb0,fb1,h0,h1}
//  v3={s0_0,s0_1,s1_0,s1_1} v4={s2_0,s2_1,s3_0,s3_1}
__device__ float4 g_pts[N_BATCH * (PPTS/2) * 5];
__device__ double g_acc;

typedef unsigned long long u64;

__device__ __forceinline__ u64 fma2(u64 a, u64 b, u64 c) {
    u64 d; asm("fma.rn.f32x2 %0, %1, %2, %3;" : "=l"(d) : "l"(a), "l"(b), "l"(c)); return d;
}
__device__ __forceinline__ u64 add2(u64 a, u64 b) {
    u64 d; asm("add.rn.f32x2 %0, %1, %2;" : "=l"(d) : "l"(a), "l"(b)); return d;
}
__device__ __forceinline__ u64 mul2(u64 a, u64 b) {
    u64 d; asm("mul.rn.f32x2 %0, %1, %2;" : "=l"(d) : "l"(a), "l"(b)); return d;
}
__device__ __forceinline__ u64 pack2(float lo, float hi) {
    u64 d; asm("mov.b64 %0, {%1, %2};" : "=l"(d) : "f"(lo), "f"(hi)); return d;
}
__device__ __forceinline__ void unpack2(u64 v, float& lo, float& hi) {
    asm("mov.b64 {%0, %1}, %2;" : "=f"(lo), "=f"(hi) : "l"(v));
}
__device__ __forceinline__ float ex2f(float a) {
    float r; asm("ex2.approx.ftz.f32 %0, %1;" : "=f"(r) : "f"(a)); return r;
}

__global__ void prep_kernel(const float* __restrict__ images,
                            const float* __restrict__ segs) {
    int idx = blockIdx.x * blockDim.x + threadIdx.x;
    if (idx == 0) g_acc = 0.0;
    if (idx >= N_BATCH * PPTS) return;
    int n = idx / PPTS;
    int p = idx % PPTS;
    int y = p / WS;
    int x = p % WS;

    const float SQL2E = 1.2011224087864498f;   // sqrt(log2(e))

    float fx = (float)x * (SQL2E / 50.0f);     // SIGMA_XY*SCALE = 50
    float fy = (float)y * (SQL2E / 50.0f);

    const float* img = images + (size_t)n * 3 * 128 * 128;
    int ro = (2 * y) * 128 + 2 * x;
    float fr = img[0 * 128 * 128 + ro] * (SQL2E / 15.0f);
    float fg = img[1 * 128 * 128 + ro] * (SQL2E / 15.0f);
    float fb = img[2 * 128 * 128 + ro] * (SQL2E / 15.0f);

    float sq = fx*fx + fy*fy + fr*fr + fg*fg + fb*fb;
    float h = -0.5f * sq;                      // -0.5*log2e*||f_unscaled||^2

    const float* sg = segs + (size_t)n * KCH * 128 * 128;
    float s[KCH];
#pragma unroll
    for (int k = 0; k < KCH; k++) {
        const float* sk = sg + (size_t)k * 128 * 128;
        s[k] = (sk[ro] + sk[ro + 1] + sk[ro + 128] + sk[ro + 129]) * 0.25f;
    }

    float* f = (float*)(g_pts + ((size_t)n * (PPTS/2) + (p >> 1)) * 5);
    int sl = p & 1;
    f[ 0 + sl] = fx;  f[ 2 + sl] = fy;
    f[ 4 + sl] = fr;  f[ 6 + sl] = fg;
    f[ 8 + sl] = fb;  f[10 + sl] = h;
    f[12 + sl] = s[0]; f[14 + sl] = s[1];
    f[16 + sl] = s[2]; f[18 + sl] = s[3];
}

__global__ void __launch_bounds__(BLOCK) crf_kernel() {
    int I = blockIdx.y;     // p tile
    int J = blockIdx.x;     // q tile
    if (J < I) return;
    int n = blockIdx.z;

    __shared__ float4 tile[NPAIR * 5];   // 10 KB
    __shared__ float wsum[BLOCK / 32];

    const float4* base = g_pts + (size_t)n * (PPTS/2) * 5;

    // Cooperative load of q tile (128 pairs * 5 float4)
    for (int i = threadIdx.x; i < NPAIR * 5; i += BLOCK)
        tile[i] = base[(size_t)J * NPAIR * 5 + i];

    // Own point p = I*TILE + tid (scalar read from pair-packed layout)
    int p = I * TILE + threadIdx.x;
    const float* f = (const float*)(base + (size_t)(p >> 1) * 5);
    int sl = p & 1;
    u64 pfx2 = pack2(f[0+sl],  f[0+sl]);
    u64 pfy2 = pack2(f[2+sl],  f[2+sl]);
    u64 pfr2 = pack2(f[4+sl],  f[4+sl]);
    u64 pfg2 = pack2(f[6+sl],  f[6+sl]);
    u64 pfb2 = pack2(f[8+sl],  f[8+sl]);
    u64 ph2  = pack2(f[10+sl], f[10+sl]);
    u64 ps02 = pack2(f[12+sl], f[12+sl]);
    u64 ps12 = pack2(f[14+sl], f[14+sl]);
    u64 ps22 = pack2(f[16+sl], f[16+sl]);
    u64 ps32 = pack2(f[18+sl], f[18+sl]);

    __syncthreads();

    u64 acc2 = pack2(0.0f, 0.0f);
#pragma unroll 4
    for (int m = 0; m < NPAIR; m++) {
        const ulonglong2* t = (const ulonglong2*)&tile[(size_t)m * 5];
        ulonglong2 u0 = t[0];   // {fx2, fy2}
        ulonglong2 u1 = t[1];   // {fr2, fg2}
        ulonglong2 u2 = t[2];   // {fb2, h2}
        ulonglong2 u3 = t[3];   // {s0q, s1q}
        ulonglong2 u4 = t[4];   // {s2q, s3q}

        u64 arg2 = add2(ph2, u2.y);
        arg2 = fma2(pfx2, u0.x, arg2);
        arg2 = fma2(pfy2, u0.y, arg2);
        arg2 = fma2(pfr2, u1.x, arg2);
        arg2 = fma2(pfg2, u1.y, arg2);
        arg2 = fma2(pfb2, u2.x, arg2);

        u64 t2 = mul2(ps02, u3.x);
        t2 = fma2(ps12, u3.y, t2);
        t2 = fma2(ps22, u4.x, t2);
        t2 = fma2(ps32, u4.y, t2);

        float a0, a1;
        unpack2(arg2, a0, a1);
        u64 e2 = pack2(ex2f(a0), ex2f(a1));
        acc2 = fma2(e2, t2, acc2);
    }

    float alo, ahi;
    unpack2(acc2, alo, ahi);
    float acc = alo + ahi;
    if (I != J) acc *= 2.0f;    // symmetric off-diagonal tile counted twice

    // Warp + block reduce
#pragma unroll
    for (int off = 16; off > 0; off >>= 1)
        acc += __shfl_down_sync(0xFFFFFFFFu, acc, off);
    int lane = threadIdx.x & 31;
    int warp = threadIdx.x >> 5;
    if (lane == 0) wsum[warp] = acc;
    __syncthreads();
    if (threadIdx.x == 0) {
        float s = 0.0f;
#pragma unroll
        for (int i = 0; i < BLOCK / 32; i++) s += wsum[i];
        atomicAdd(&g_acc, (double)s);
    }
}

__global__ void finish_kernel(float* __restrict__ out) {
    // loss = WEIGHT * (-sum / N_BATCH)
    out[0] = (float)(g_acc * (-1e-7 / (double)N_BATCH));
}

extern "C" void kernel_launch(void* const* d_in, const int* in_sizes, int n_in,
                              void* d_out, int out_size) {
    const float* images = (const float*)d_in[0];
    const float* segs   = (const float*)d_in[1];

    prep_kernel<<<(N_BATCH * PPTS + 255) / 256, 256>>>(images, segs);

    dim3 grid(NTILES, NTILES, N_BATCH);
    crf_kernel<<<grid, BLOCK>>>();

    finish_kernel<<<1, 1>>>((float*)d_out);
}